// round 14
// baseline (speedup 1.0000x reference)
#include <cuda_runtime.h>
#include <cuda_fp16.h>
#include <mma.h>
#include <math.h>

using namespace nvcuda;

#define NN 100000
#define EE 1600000
#define DDIM 64
#define GGR 2000

// Scratch (allocation-free rule: __device__ globals)
__device__ float  g_a[NN * DDIM];     // final fp32 features
__device__ __half g_ha[NN * DDIM];    // fp16 feature ping
__device__ __half g_hb[NN * DDIM];    // fp16 feature pong
__device__ __half g_hh[NN * DDIM];    // gathered h (pre-MLP)
__device__ float  g_gate[NN];
__device__ int    g_deg[NN];
__device__ int    g_rs[NN];
__device__ int    g_pos[EE];
__device__ int    g_csr[EE];
__device__ int    g_total;
// Pre-converted fp16 weights in padded ldm=72 smem layout (per layer 64x72)
__device__ __half g_w1h[3 * 64 * 72];
__device__ __half g_w2h[3 * 64 * 72];

// ---------------------------------------------------------------------------
// k_pre: zero deg/total + fp32->fp16 feature conversion
// ---------------------------------------------------------------------------
__global__ void k_pre(const float* __restrict__ X, __half* __restrict__ Xh,
                      int* __restrict__ deg, int total4, int n) {
    int i = blockIdx.x * blockDim.x + threadIdx.x;
    if (i == 0) g_total = 0;
    if (i < n) deg[i] = 0;
    if (i >= total4) return;
    float4 v = ((const float4*)X)[i];
    __half2 p0 = __floats2half2_rn(v.x, v.y);
    __half2 p1 = __floats2half2_rn(v.z, v.w);
    uint2 o; o.x = *(unsigned*)&p0; o.y = *(unsigned*)&p1;
    ((uint2*)Xh)[i] = o;
}

// Weight pre-conversion: fp32 [3][64][64] -> fp16 padded [3][64 x ldm72]
__global__ void k_wcvt(const float* __restrict__ W1, const float* __restrict__ W2,
                       __half* __restrict__ w1h, __half* __restrict__ w2h) {
    int i = blockIdx.x * blockDim.x + threadIdx.x;
    if (i >= 3 * 4096) return;
    int l = i >> 12, idx = i & 4095;
    int k = idx >> 6, nn = idx & 63;
    int o = l * 4608 + k * 72 + nn;
    w1h[o] = __float2half(W1[i]);
    w2h[o] = __float2half(W2[i]);
}

// ---------------------------------------------------------------------------
// CSR build
// ---------------------------------------------------------------------------
__global__ void k_hist(const int* __restrict__ dst, int* __restrict__ deg,
                       int* __restrict__ pos, int e) {
    int i = blockIdx.x * blockDim.x + threadIdx.x;
    if (i >= e) return;
    pos[i] = atomicAdd(&deg[__ldg(&dst[i])], 1);
}

__global__ void __launch_bounds__(256) k_alloc(
    const int* __restrict__ deg, int* __restrict__ rs, int n) {
    __shared__ int sdata[256];
    __shared__ int base;
    int tx = threadIdx.x;
    int i = blockIdx.x * 256 + tx;
    int d = (i < n) ? deg[i] : 0;
    sdata[tx] = d;
    __syncthreads();
    #pragma unroll
    for (int o = 1; o < 256; o <<= 1) {
        int t = (tx >= o) ? sdata[tx - o] : 0;
        __syncthreads();
        sdata[tx] += t;
        __syncthreads();
    }
    int incl = sdata[tx];
    if (tx == 255) base = atomicAdd(&g_total, incl);
    __syncthreads();
    if (i < n) rs[i] = base + incl - d;
}

__global__ void k_fill(const int* __restrict__ src, const int* __restrict__ dst,
                       const int* __restrict__ pos, const int* __restrict__ rs,
                       int* __restrict__ csr, int e) {
    int i = blockIdx.x * blockDim.x + threadIdx.x;
    if (i >= e) return;
    int d = __ldg(&dst[i]);
    csr[__ldg(&rs[d]) + __ldg(&pos[i])] = __ldg(&src[i]);
}

// ---------------------------------------------------------------------------
// Barrier-free gather: h = (1+eps)*x + sum_{j in N(i)} x[j], fp16 out.
// Half-warp (16 lanes) per row, lane `sub` owns dims sub*4..sub*4+3.
// No smem, no syncs -> degree imbalance only costs at the grid tail.
// ---------------------------------------------------------------------------
__global__ void __launch_bounds__(256) k_gather(
    const __half* __restrict__ Xh, __half* __restrict__ H,
    const int* __restrict__ deg, const int* __restrict__ rs,
    const int* __restrict__ csr,
    const float* __restrict__ eps, int l, int n) {
    int t = blockIdx.x * 256 + threadIdx.x;
    int row = t >> 4;
    int sub = t & 15;
    if (row >= n) return;
    float se = 1.0f + __ldg(&eps[l]);

    uint2 sv = *(const uint2*)(Xh + (size_t)row * 64 + sub * 4);
    float2 f01 = __half22float2(*(__half2*)&sv.x);
    float2 f23 = __half22float2(*(__half2*)&sv.y);
    float4 A0, A1, A2, A3;
    A0.x = f01.x * se; A0.y = f01.y * se;
    A0.z = f23.x * se; A0.w = f23.y * se;
    A1 = make_float4(0.f, 0.f, 0.f, 0.f); A2 = A1; A3 = A1;

    int start = __ldg(&rs[row]);
    int d = __ldg(&deg[row]);
    int tt = 0;
    for (; tt + 4 <= d; tt += 4) {
        int j0 = __ldg(&csr[start + tt + 0]);
        int j1 = __ldg(&csr[start + tt + 1]);
        int j2 = __ldg(&csr[start + tt + 2]);
        int j3 = __ldg(&csr[start + tt + 3]);
        uint2 v0 = *(const uint2*)(Xh + (size_t)j0 * 64 + sub * 4);
        uint2 v1 = *(const uint2*)(Xh + (size_t)j1 * 64 + sub * 4);
        uint2 v2 = *(const uint2*)(Xh + (size_t)j2 * 64 + sub * 4);
        uint2 v3 = *(const uint2*)(Xh + (size_t)j3 * 64 + sub * 4);
        float2 a, b;
        a = __half22float2(*(__half2*)&v0.x); b = __half22float2(*(__half2*)&v0.y);
        A0.x += a.x; A0.y += a.y; A0.z += b.x; A0.w += b.y;
        a = __half22float2(*(__half2*)&v1.x); b = __half22float2(*(__half2*)&v1.y);
        A1.x += a.x; A1.y += a.y; A1.z += b.x; A1.w += b.y;
        a = __half22float2(*(__half2*)&v2.x); b = __half22float2(*(__half2*)&v2.y);
        A2.x += a.x; A2.y += a.y; A2.z += b.x; A2.w += b.y;
        a = __half22float2(*(__half2*)&v3.x); b = __half22float2(*(__half2*)&v3.y);
        A3.x += a.x; A3.y += a.y; A3.z += b.x; A3.w += b.y;
    }
    for (; tt < d; tt++) {
        int j = __ldg(&csr[start + tt]);
        uint2 v = *(const uint2*)(Xh + (size_t)j * 64 + sub * 4);
        float2 a = __half22float2(*(__half2*)&v.x);
        float2 b = __half22float2(*(__half2*)&v.y);
        A0.x += a.x; A0.y += a.y; A0.z += b.x; A0.w += b.y;
    }
    A0.x += A1.x + A2.x + A3.x;
    A0.y += A1.y + A2.y + A3.y;
    A0.z += A1.z + A2.z + A3.z;
    A0.w += A1.w + A2.w + A3.w;

    __half2 p0 = __floats2half2_rn(A0.x, A0.y);
    __half2 p1 = __floats2half2_rn(A0.z, A0.w);
    *(uint2*)(H + (size_t)row * 64 + sub * 4) = make_uint2(*(unsigned*)&p0, *(unsigned*)&p1);
}

// ---------------------------------------------------------------------------
// MLP: tile load (coalesced) + tensor-core GEMMs (wmma, conflict-free smem)
// + fp32 LayerNorm (+ fused attention gate on the last layer).
// Block 256 threads = 8 warps; tile = 64 nodes x 64 dims.
// ---------------------------------------------------------------------------
__global__ void __launch_bounds__(256) k_mlp(
    const __half* __restrict__ H,
    const __half* __restrict__ W1h, const float* __restrict__ B1,
    const __half* __restrict__ W2h, const float* __restrict__ B2,
    const float* __restrict__ LG, const float* __restrict__ LB,
    const float* __restrict__ GW1, const float* __restrict__ GB1,
    const float* __restrict__ GW2, const float* __restrict__ GB2,
    float* __restrict__ gate, int l,
    float* __restrict__ Of, __half* __restrict__ Oh, int n) {
    __shared__ __align__(16) __half sW1h[64 * 72];  // ldm 72: LDSM conflict-free
    __shared__ __align__(16) __half sW2h[64 * 72];
    __shared__ __align__(16) __half sHh[64 * 72];
    __shared__ __align__(16) float  sT[64 * 68];

    int tid = threadIdx.x;
    int n0 = blockIdx.x * 64;

    // pre-converted fp16 weights -> smem (straight uint4 copy)
    {
        const __half* w1p = W1h + l * 4608;
        const __half* w2p = W2h + l * 4608;
        #pragma unroll
        for (int i = tid * 8; i < 4608; i += 2048) {
            *(uint4*)(&sW1h[i]) = *(const uint4*)(w1p + i);
            *(uint4*)(&sW2h[i]) = *(const uint4*)(w2p + i);
        }
    }

    // tile load: 64 rows x 128B, coalesced, restructured to ldm 72
    {
        const uint4* Hp = (const uint4*)(H + (size_t)n0 * 64);
        #pragma unroll
        for (int i = tid; i < 512; i += 256) {
            int r = i >> 3, c = i & 7;
            uint4 v = make_uint4(0u, 0u, 0u, 0u);
            if (n0 + r < n) v = Hp[i];
            *(uint4*)(&sHh[r * 72 + c * 8]) = v;
        }
    }
    __syncthreads();

    // warp tile assignment: warp w -> m-tile w>>1, n-tiles (w&1)*2, (w&1)*2+1
    int w = tid >> 5;
    int mt = w >> 1, nt0 = (w & 1) * 2;

    // GEMM1: T = Hh @ W1  (HMMA fp32 accum)
    {
        wmma::fragment<wmma::accumulator, 16, 16, 16, float> c[2];
        wmma::fill_fragment(c[0], 0.0f);
        wmma::fill_fragment(c[1], 0.0f);
        #pragma unroll
        for (int k = 0; k < 4; k++) {
            wmma::fragment<wmma::matrix_a, 16, 16, 16, __half, wmma::row_major> a;
            wmma::load_matrix_sync(a, &sHh[mt * 16 * 72 + k * 16], 72);
            #pragma unroll
            for (int t = 0; t < 2; t++) {
                wmma::fragment<wmma::matrix_b, 16, 16, 16, __half, wmma::row_major> b;
                wmma::load_matrix_sync(b, &sW1h[(k * 16) * 72 + (nt0 + t) * 16], 72);
                wmma::mma_sync(c[t], a, b, c[t]);
            }
        }
        wmma::store_matrix_sync(&sT[mt * 16 * 68 + (nt0 + 0) * 16], c[0], 68, wmma::mem_row_major);
        wmma::store_matrix_sync(&sT[mt * 16 * 68 + (nt0 + 1) * 16], c[1], 68, wmma::mem_row_major);
    }
    __syncthreads();

    // bias + silu -> sHh (fp16). On last layer, also stage gw1 into sW1h space.
    for (int i = tid; i < 4096; i += 256) {
        int r = i >> 6, cc = i & 63;
        float t = sT[r * 68 + cc] + __ldg(&B1[cc]);
        float s = t / (1.f + __expf(-t));
        sHh[r * 72 + cc] = __float2half(s);
    }
    float* gw1s = (float*)sW1h;  // 2048 floats fit in 9216B
    if (Of) {
        for (int i = tid; i < 2048; i += 256) gw1s[i] = __ldg(&GW1[i]);
    }
    __syncthreads();

    // GEMM2: U = silu(T) @ W2
    {
        wmma::fragment<wmma::accumulator, 16, 16, 16, float> c[2];
        wmma::fill_fragment(c[0], 0.0f);
        wmma::fill_fragment(c[1], 0.0f);
        #pragma unroll
        for (int k = 0; k < 4; k++) {
            wmma::fragment<wmma::matrix_a, 16, 16, 16, __half, wmma::row_major> a;
            wmma::load_matrix_sync(a, &sHh[mt * 16 * 72 + k * 16], 72);
            #pragma unroll
            for (int t = 0; t < 2; t++) {
                wmma::fragment<wmma::matrix_b, 16, 16, 16, __half, wmma::row_major> b;
                wmma::load_matrix_sync(b, &sW2h[(k * 16) * 72 + (nt0 + t) * 16], 72);
                wmma::mma_sync(c[t], a, b, c[t]);
            }
        }
        wmma::store_matrix_sync(&sT[mt * 16 * 68 + (nt0 + 0) * 16], c[0], 68, wmma::mem_row_major);
        wmma::store_matrix_sync(&sT[mt * 16 * 68 + (nt0 + 1) * 16], c[1], 68, wmma::mem_row_major);
    }
    __syncthreads();

    // LayerNorm per row (fp32); writes output and (for gate) normalized sT
    {
        int tx = tid & 15, ty = tid >> 4;
        int r0 = ty * 4, c0 = tx * 4;
        float4 bb2 = *(const float4*)(B2 + c0);
        float4 g4 = *(const float4*)(LG + c0);
        float4 lb4 = *(const float4*)(LB + c0);
        #pragma unroll
        for (int j = 0; j < 4; j++) {
            float4 u4 = *(float4*)(&sT[(r0 + j) * 68 + c0]);
            float u0 = u4.x + bb2.x, u1 = u4.y + bb2.y;
            float u2 = u4.z + bb2.z, u3 = u4.w + bb2.w;
            float s = u0 + u1 + u2 + u3;
            #pragma unroll
            for (int o = 1; o < 16; o <<= 1) s += __shfl_xor_sync(0xffffffffu, s, o);
            float mu = s * (1.f / 64.f);
            float d0 = u0 - mu, d1 = u1 - mu, d2 = u2 - mu, d3 = u3 - mu;
            float q = d0 * d0 + d1 * d1 + d2 * d2 + d3 * d3;
            #pragma unroll
            for (int o = 1; o < 16; o <<= 1) q += __shfl_xor_sync(0xffffffffu, q, o);
            float rstd = rsqrtf(q * (1.f / 64.f) + 1e-5f);
            int row = n0 + r0 + j;
            float4 o4;
            o4.x = d0 * rstd * g4.x + lb4.x;
            o4.y = d1 * rstd * g4.y + lb4.y;
            o4.z = d2 * rstd * g4.z + lb4.z;
            o4.w = d3 * rstd * g4.w + lb4.w;
            if (row < n) {
                if (Of) *(float4*)(Of + (size_t)row * 64 + c0) = o4;
                if (Oh) {
                    __half2 p0 = __floats2half2_rn(o4.x, o4.y);
                    __half2 p1 = __floats2half2_rn(o4.z, o4.w);
                    uint2 ho; ho.x = *(unsigned*)&p0; ho.y = *(unsigned*)&p1;
                    *(uint2*)(Oh + row * 64 + c0) = ho;
                }
            }
            if (Of) *(float4*)(&sT[(r0 + j) * 68 + c0]) = o4;  // stage for gate
        }
    }

    // Fused attention gate (last layer only): gate = silu(x@gw1+gb1)@gw2+gb2
    if (Of) {
        __syncthreads();
        int lane = tid & 31;
        float gb1v = __ldg(&GB1[lane]);
        float gw2v = __ldg(&GW2[lane]);
        float gb2v = __ldg(&GB2[0]);
        int rbase = w * 8;
        float acc[8];
        #pragma unroll
        for (int r = 0; r < 8; r++) acc[r] = gb1v;
        #pragma unroll 4
        for (int k0 = 0; k0 < 64; k0 += 4) {
            float w0 = gw1s[(k0 + 0) * 32 + lane];
            float w1 = gw1s[(k0 + 1) * 32 + lane];
            float w2 = gw1s[(k0 + 2) * 32 + lane];
            float w3 = gw1s[(k0 + 3) * 32 + lane];
            #pragma unroll
            for (int r = 0; r < 8; r++) {
                float4 xv = *(float4*)(&sT[(rbase + r) * 68 + k0]);
                acc[r] += xv.x * w0 + xv.y * w1 + xv.z * w2 + xv.w * w3;
            }
        }
        #pragma unroll
        for (int r = 0; r < 8; r++) {
            float t = acc[r];
            float sil = t / (1.f + __expf(-t));
            float v = sil * gw2v;
            #pragma unroll
            for (int o = 16; o > 0; o >>= 1) v += __shfl_xor_sync(0xffffffffu, v, o);
            int row = n0 + rbase + r;
            if (lane == 0 && row < n) gate[row] = v + gb2v;
        }
    }
}

// ---------------------------------------------------------------------------
// Per-graph softmax attention pool (batch sorted -> binary-search segment)
// ---------------------------------------------------------------------------
__global__ void k_pool(const float* __restrict__ X, const float* __restrict__ gate,
                       const int* __restrict__ batch, float* __restrict__ out, int n) {
    int g = blockIdx.x;
    int tid = threadIdx.x;  // 64 threads

    int lo = 0, hi = n;
    while (lo < hi) { int mid = (lo + hi) >> 1; if (batch[mid] < g) lo = mid + 1; else hi = mid; }
    int start = lo;
    lo = start; hi = n;
    while (lo < hi) { int mid = (lo + hi) >> 1; if (batch[mid] < g + 1) lo = mid + 1; else hi = mid; }
    int end = lo;

    if (start >= end) { out[(size_t)g * 64 + tid] = 0.f; return; }

    __shared__ float wred[2];
    __shared__ float sw[128];
    float m = -3.402823e38f;
    for (int i = start + tid; i < end; i += 64) m = fmaxf(m, gate[i]);
    #pragma unroll
    for (int o = 16; o > 0; o >>= 1) m = fmaxf(m, __shfl_xor_sync(0xffffffffu, m, o));
    if ((tid & 31) == 0) wred[tid >> 5] = m;
    __syncthreads();
    m = fmaxf(wred[0], wred[1]);
    __syncthreads();
    float s = 0.f;
    for (int i = start + tid; i < end; i += 64) s += __expf(gate[i] - m);
    #pragma unroll
    for (int o = 16; o > 0; o >>= 1) s += __shfl_xor_sync(0xffffffffu, s, o);
    if ((tid & 31) == 0) wred[tid >> 5] = s;
    __syncthreads();
    float inv = 1.f / (wred[0] + wred[1]);

    float acc = 0.f;
    for (int chunk = start; chunk < end; chunk += 128) {
        int cnt = min(128, end - chunk);
        __syncthreads();
        for (int i = tid; i < cnt; i += 64) sw[i] = __expf(gate[chunk + i] - m);
        __syncthreads();
        for (int k = 0; k < cnt; k++)
            acc += sw[k] * X[(size_t)(chunk + k) * 64 + tid];
    }
    out[(size_t)g * 64 + tid] = acc * inv;
}

// ---------------------------------------------------------------------------
extern "C" void kernel_launch(void* const* d_in, const int* in_sizes, int n_in,
                              void* d_out, int out_size) {
    const float* x   = (const float*)d_in[0];
    const int*   ei  = (const int*)d_in[1];
    const int*   bat = (const int*)d_in[2];
    const float* W1  = (const float*)d_in[3];
    const float* b1  = (const float*)d_in[4];
    const float* W2  = (const float*)d_in[5];
    const float* b2  = (const float*)d_in[6];
    const float* eps = (const float*)d_in[7];
    const float* lng = (const float*)d_in[8];
    const float* lnb = (const float*)d_in[9];
    const float* gw1 = (const float*)d_in[10];
    const float* gb1 = (const float*)d_in[11];
    const float* gw2 = (const float*)d_in[12];
    const float* gb2 = (const float*)d_in[13];
    float* out = (float*)d_out;

    int n = in_sizes[0] / DDIM;
    int e = in_sizes[1] / 2;
    int g = out_size / DDIM;
    const int* src = ei;
    const int* dst = ei + e;

    float *ga, *ggate;
    __half *ha, *hb, *hh, *w1h, *w2h;
    int *deg, *rsa, *pos, *csr;
    cudaGetSymbolAddress((void**)&ga, g_a);
    cudaGetSymbolAddress((void**)&ha, g_ha);
    cudaGetSymbolAddress((void**)&hb, g_hb);
    cudaGetSymbolAddress((void**)&hh, g_hh);
    cudaGetSymbolAddress((void**)&ggate, g_gate);
    cudaGetSymbolAddress((void**)&deg, g_deg);
    cudaGetSymbolAddress((void**)&rsa, g_rs);
    cudaGetSymbolAddress((void**)&pos, g_pos);
    cudaGetSymbolAddress((void**)&csr, g_csr);
    cudaGetSymbolAddress((void**)&w1h, g_w1h);
    cudaGetSymbolAddress((void**)&w2h, g_w2h);

    int total4 = n * (DDIM / 4);
    k_wcvt<<<(3 * 4096 + 255) / 256, 256>>>(W1, W2, w1h, w2h);
    k_pre<<<(total4 + 255) / 256, 256>>>(x, hb, deg, total4, n);
    k_hist<<<(e + 255) / 256, 256>>>(dst, deg, pos, e);
    k_alloc<<<(n + 255) / 256, 256>>>(deg, rsa, n);
    k_fill<<<(e + 255) / 256, 256>>>(src, dst, pos, rsa, csr, e);

    int nblk = (n + 63) / 64;
    int gblk = (n * 16 + 255) / 256;

    // layer 0: hb -> hh -> ha
    k_gather<<<gblk, 256>>>(hb, hh, deg, rsa, csr, eps, 0, n);
    k_mlp<<<nblk, 256>>>(hh, w1h, b1, w2h, b2, lng, lnb,
                         gw1, gb1, gw2, gb2, ggate, 0,
                         (float*)nullptr, ha, n);
    // layer 1: ha -> hh -> hb
    k_gather<<<gblk, 256>>>(ha, hh, deg, rsa, csr, eps, 1, n);
    k_mlp<<<nblk, 256>>>(hh, w1h, b1 + 64, w2h, b2 + 64, lng + 64, lnb + 64,
                         gw1, gb1, gw2, gb2, ggate, 1,
                         (float*)nullptr, hb, n);
    // layer 2: hb -> hh -> ga (+gate)
    k_gather<<<gblk, 256>>>(hb, hh, deg, rsa, csr, eps, 2, n);
    k_mlp<<<nblk, 256>>>(hh, w1h, b1 + 128, w2h, b2 + 128, lng + 128, lnb + 128,
                         gw1, gb1, gw2, gb2, ggate, 2,
                         ga, (__half*)nullptr, n);

    k_pool<<<g, 64>>>(ga, ggate, bat, out, n);
}

// round 16
// speedup vs baseline: 1.0946x; 1.0946x over previous
#include <cuda_runtime.h>
#include <cuda_fp16.h>
#include <mma.h>
#include <math.h>

using namespace nvcuda;

#define NN 100000
#define EE 1600000
#define DDIM 64
#define GGR 2000

// Scratch (allocation-free rule: __device__ globals)
__device__ __half g_ha[NN * DDIM];    // fp16 feature ping
__device__ __half g_hb[NN * DDIM];    // fp16 feature pong
__device__ float  g_gate[NN];
__device__ int    g_deg[NN];
__device__ int    g_rs[NN];
__device__ int    g_pos[EE];
__device__ int    g_csr[EE];
__device__ int    g_total;

// ---------------------------------------------------------------------------
// k_pre: zero deg/total + fp32->fp16 feature conversion
// ---------------------------------------------------------------------------
__global__ void k_pre(const float* __restrict__ X, __half* __restrict__ Xh,
                      int* __restrict__ deg, int total4, int n) {
    int i = blockIdx.x * blockDim.x + threadIdx.x;
    if (i == 0) g_total = 0;
    if (i < n) deg[i] = 0;
    if (i >= total4) return;
    float4 v = ((const float4*)X)[i];
    __half2 p0 = __floats2half2_rn(v.x, v.y);
    __half2 p1 = __floats2half2_rn(v.z, v.w);
    uint2 o; o.x = *(unsigned*)&p0; o.y = *(unsigned*)&p1;
    ((uint2*)Xh)[i] = o;
}

// ---------------------------------------------------------------------------
// CSR build
// ---------------------------------------------------------------------------
__global__ void k_hist(const int* __restrict__ dst, int* __restrict__ deg,
                       int* __restrict__ pos, int e) {
    int i = blockIdx.x * blockDim.x + threadIdx.x;
    if (i >= e) return;
    pos[i] = atomicAdd(&deg[__ldg(&dst[i])], 1);
}

__global__ void __launch_bounds__(256) k_alloc(
    const int* __restrict__ deg, int* __restrict__ rs, int n) {
    __shared__ int sdata[256];
    __shared__ int base;
    int tx = threadIdx.x;
    int i = blockIdx.x * 256 + tx;
    int d = (i < n) ? deg[i] : 0;
    sdata[tx] = d;
    __syncthreads();
    #pragma unroll
    for (int o = 1; o < 256; o <<= 1) {
        int t = (tx >= o) ? sdata[tx - o] : 0;
        __syncthreads();
        sdata[tx] += t;
        __syncthreads();
    }
    int incl = sdata[tx];
    if (tx == 255) base = atomicAdd(&g_total, incl);
    __syncthreads();
    if (i < n) rs[i] = base + incl - d;
}

__global__ void k_fill(const int* __restrict__ src, const int* __restrict__ dst,
                       const int* __restrict__ pos, const int* __restrict__ rs,
                       int* __restrict__ csr, int e) {
    int i = blockIdx.x * blockDim.x + threadIdx.x;
    if (i >= e) return;
    int d = __ldg(&dst[i]);
    csr[__ldg(&rs[d]) + __ldg(&pos[i])] = __ldg(&src[i]);
}

// ---------------------------------------------------------------------------
// Fused: fp16 gather (pairwise HADD2 pre-reduce, fp32 accumulate) +
// tensor-core MLP (wmma, conflict-free smem) + fp32 LayerNorm
// (+ fused attention gate on the last layer). All layers emit fp16.
// Block 256 threads = 8 warps; tile = 64 nodes x 64 dims.
// ---------------------------------------------------------------------------
__global__ void __launch_bounds__(256) k_mlp(
    const __half* __restrict__ Xh,
    const int* __restrict__ deg, const int* __restrict__ rs, const int* __restrict__ csr,
    const float* __restrict__ eps, int l,
    const float* __restrict__ W1, const float* __restrict__ B1,
    const float* __restrict__ W2, const float* __restrict__ B2,
    const float* __restrict__ LG, const float* __restrict__ LB,
    const float* __restrict__ GW1, const float* __restrict__ GB1,
    const float* __restrict__ GW2, const float* __restrict__ GB2,
    float* __restrict__ gate, int last,
    __half* __restrict__ Oh, int n) {
    __shared__ __align__(16) __half sW1h[64 * 72];  // ldm 72: LDSM conflict-free
    __shared__ __align__(16) __half sW2h[64 * 72];
    __shared__ __align__(16) __half sHh[64 * 72];
    __shared__ __align__(16) float  sT[64 * 68];

    int tid = threadIdx.x;
    int n0 = blockIdx.x * 64;

    // W1, W2 -> fp16 smem (row k, ldm 72)
    #pragma unroll
    for (int i = tid * 4; i < 4096; i += 1024) {
        int k = i >> 6, nn = i & 63;
        float4 w = *(const float4*)(W1 + i);
        __half2 p0 = __floats2half2_rn(w.x, w.y);
        __half2 p1 = __floats2half2_rn(w.z, w.w);
        *(uint2*)(&sW1h[k * 72 + nn]) = make_uint2(*(unsigned*)&p0, *(unsigned*)&p1);
        float4 v = *(const float4*)(W2 + i);
        __half2 q0 = __floats2half2_rn(v.x, v.y);
        __half2 q1 = __floats2half2_rn(v.z, v.w);
        *(uint2*)(&sW2h[k * 72 + nn]) = make_uint2(*(unsigned*)&q0, *(unsigned*)&q1);
    }

    // gather: warp handles 2 rows concurrently (half-warp of 16 lanes per row,
    // lane `sub` owns dims sub*4..sub*4+3). 4-neighbor chunks: pairwise fp16
    // add (HADD2) then fp32 accumulate — 20 ops/4-neighbors instead of 32.
    {
        int lane = tid & 31, w = tid >> 5;
        int sub = lane & 15, hw = lane >> 4;
        float se = 1.0f + __ldg(&eps[l]);
        #pragma unroll
        for (int it = 0; it < 4; it++) {
            int r = it * 16 + w * 2 + hw;
            int node = n0 + r;
            float4 A0 = make_float4(0.f, 0.f, 0.f, 0.f), A1 = A0;
            if (node < n) {
                uint2 sv = *(const uint2*)(Xh + (size_t)node * 64 + sub * 4);
                float2 f01 = __half22float2(*(__half2*)&sv.x);
                float2 f23 = __half22float2(*(__half2*)&sv.y);
                A0.x = f01.x * se; A0.y = f01.y * se;
                A0.z = f23.x * se; A0.w = f23.y * se;
                int start = __ldg(&rs[node]);
                int d = __ldg(&deg[node]);
                int t = 0;
                for (; t + 4 <= d; t += 4) {
                    int j0 = __ldg(&csr[start + t + 0]);
                    int j1 = __ldg(&csr[start + t + 1]);
                    int j2 = __ldg(&csr[start + t + 2]);
                    int j3 = __ldg(&csr[start + t + 3]);
                    uint2 v0 = *(const uint2*)(Xh + (size_t)j0 * 64 + sub * 4);
                    uint2 v1 = *(const uint2*)(Xh + (size_t)j1 * 64 + sub * 4);
                    uint2 v2 = *(const uint2*)(Xh + (size_t)j2 * 64 + sub * 4);
                    uint2 v3 = *(const uint2*)(Xh + (size_t)j3 * 64 + sub * 4);
                    __half2 p0 = __hadd2(*(__half2*)&v0.x, *(__half2*)&v1.x);
                    __half2 p1 = __hadd2(*(__half2*)&v0.y, *(__half2*)&v1.y);
                    __half2 q0 = __hadd2(*(__half2*)&v2.x, *(__half2*)&v3.x);
                    __half2 q1 = __hadd2(*(__half2*)&v2.y, *(__half2*)&v3.y);
                    float2 a = __half22float2(p0), b = __half22float2(p1);
                    A0.x += a.x; A0.y += a.y; A0.z += b.x; A0.w += b.y;
                    a = __half22float2(q0); b = __half22float2(q1);
                    A1.x += a.x; A1.y += a.y; A1.z += b.x; A1.w += b.y;
                }
                for (; t < d; t++) {
                    int j = __ldg(&csr[start + t]);
                    uint2 v = *(const uint2*)(Xh + (size_t)j * 64 + sub * 4);
                    float2 a = __half22float2(*(__half2*)&v.x);
                    float2 b = __half22float2(*(__half2*)&v.y);
                    A0.x += a.x; A0.y += a.y; A0.z += b.x; A0.w += b.y;
                }
                A0.x += A1.x; A0.y += A1.y; A0.z += A1.z; A0.w += A1.w;
            }
            __half2 p0 = __floats2half2_rn(A0.x, A0.y);
            __half2 p1 = __floats2half2_rn(A0.z, A0.w);
            *(uint2*)(&sHh[r * 72 + sub * 4]) = make_uint2(*(unsigned*)&p0, *(unsigned*)&p1);
        }
    }
    __syncthreads();

    // warp tile assignment: warp w -> m-tile w>>1, n-tiles (w&1)*2, (w&1)*2+1
    int w = tid >> 5;
    int mt = w >> 1, nt0 = (w & 1) * 2;

    // GEMM1: T = Hh @ W1  (HMMA fp32 accum)
    {
        wmma::fragment<wmma::accumulator, 16, 16, 16, float> c[2];
        wmma::fill_fragment(c[0], 0.0f);
        wmma::fill_fragment(c[1], 0.0f);
        #pragma unroll
        for (int k = 0; k < 4; k++) {
            wmma::fragment<wmma::matrix_a, 16, 16, 16, __half, wmma::row_major> a;
            wmma::load_matrix_sync(a, &sHh[mt * 16 * 72 + k * 16], 72);
            #pragma unroll
            for (int t = 0; t < 2; t++) {
                wmma::fragment<wmma::matrix_b, 16, 16, 16, __half, wmma::row_major> b;
                wmma::load_matrix_sync(b, &sW1h[(k * 16) * 72 + (nt0 + t) * 16], 72);
                wmma::mma_sync(c[t], a, b, c[t]);
            }
        }
        wmma::store_matrix_sync(&sT[mt * 16 * 68 + (nt0 + 0) * 16], c[0], 68, wmma::mem_row_major);
        wmma::store_matrix_sync(&sT[mt * 16 * 68 + (nt0 + 1) * 16], c[1], 68, wmma::mem_row_major);
    }
    __syncthreads();

    // bias + silu -> sHh (fp16). On last layer, also stage gw1 into sW1h space.
    for (int i = tid; i < 4096; i += 256) {
        int r = i >> 6, cc = i & 63;
        float t = sT[r * 68 + cc] + __ldg(&B1[cc]);
        float s = t / (1.f + __expf(-t));
        sHh[r * 72 + cc] = __float2half(s);
    }
    float* gw1s = (float*)sW1h;  // 2048 floats fit in 9216B
    if (last) {
        for (int i = tid; i < 2048; i += 256) gw1s[i] = __ldg(&GW1[i]);
    }
    __syncthreads();

    // GEMM2: U = silu(T) @ W2
    {
        wmma::fragment<wmma::accumulator, 16, 16, 16, float> c[2];
        wmma::fill_fragment(c[0], 0.0f);
        wmma::fill_fragment(c[1], 0.0f);
        #pragma unroll
        for (int k = 0; k < 4; k++) {
            wmma::fragment<wmma::matrix_a, 16, 16, 16, __half, wmma::row_major> a;
            wmma::load_matrix_sync(a, &sHh[mt * 16 * 72 + k * 16], 72);
            #pragma unroll
            for (int t = 0; t < 2; t++) {
                wmma::fragment<wmma::matrix_b, 16, 16, 16, __half, wmma::row_major> b;
                wmma::load_matrix_sync(b, &sW2h[(k * 16) * 72 + (nt0 + t) * 16], 72);
                wmma::mma_sync(c[t], a, b, c[t]);
            }
        }
        wmma::store_matrix_sync(&sT[mt * 16 * 68 + (nt0 + 0) * 16], c[0], 68, wmma::mem_row_major);
        wmma::store_matrix_sync(&sT[mt * 16 * 68 + (nt0 + 1) * 16], c[1], 68, wmma::mem_row_major);
    }
    __syncthreads();

    // LayerNorm per row (fp32); fp16 output; (for gate) stage normalized sT
    {
        int tx = tid & 15, ty = tid >> 4;
        int r0 = ty * 4, c0 = tx * 4;
        float4 bb2 = *(const float4*)(B2 + c0);
        float4 g4 = *(const float4*)(LG + c0);
        float4 lb4 = *(const float4*)(LB + c0);
        #pragma unroll
        for (int j = 0; j < 4; j++) {
            float4 u4 = *(float4*)(&sT[(r0 + j) * 68 + c0]);
            float u0 = u4.x + bb2.x, u1 = u4.y + bb2.y;
            float u2 = u4.z + bb2.z, u3 = u4.w + bb2.w;
            float s = u0 + u1 + u2 + u3;
            #pragma unroll
            for (int o = 1; o < 16; o <<= 1) s += __shfl_xor_sync(0xffffffffu, s, o);
            float mu = s * (1.f / 64.f);
            float d0 = u0 - mu, d1 = u1 - mu, d2 = u2 - mu, d3 = u3 - mu;
            float q = d0 * d0 + d1 * d1 + d2 * d2 + d3 * d3;
            #pragma unroll
            for (int o = 1; o < 16; o <<= 1) q += __shfl_xor_sync(0xffffffffu, q, o);
            float rstd = rsqrtf(q * (1.f / 64.f) + 1e-5f);
            int row = n0 + r0 + j;
            float4 o4;
            o4.x = d0 * rstd * g4.x + lb4.x;
            o4.y = d1 * rstd * g4.y + lb4.y;
            o4.z = d2 * rstd * g4.z + lb4.z;
            o4.w = d3 * rstd * g4.w + lb4.w;
            if (row < n) {
                __half2 p0 = __floats2half2_rn(o4.x, o4.y);
                __half2 p1 = __floats2half2_rn(o4.z, o4.w);
                uint2 ho; ho.x = *(unsigned*)&p0; ho.y = *(unsigned*)&p1;
                *(uint2*)(Oh + (size_t)row * 64 + c0) = ho;
            }
            if (last) *(float4*)(&sT[(r0 + j) * 68 + c0]) = o4;  // stage for gate
        }
    }

    // Fused attention gate (last layer only): gate = silu(x@gw1+gb1)@gw2+gb2
    if (last) {
        __syncthreads();
        int lane = tid & 31;
        float gb1v = __ldg(&GB1[lane]);
        float gw2v = __ldg(&GW2[lane]);
        float gb2v = __ldg(&GB2[0]);
        int rbase = w * 8;
        float acc[8];
        #pragma unroll
        for (int r = 0; r < 8; r++) acc[r] = gb1v;
        #pragma unroll 4
        for (int k0 = 0; k0 < 64; k0 += 4) {
            float w0 = gw1s[(k0 + 0) * 32 + lane];
            float w1 = gw1s[(k0 + 1) * 32 + lane];
            float w2 = gw1s[(k0 + 2) * 32 + lane];
            float w3 = gw1s[(k0 + 3) * 32 + lane];
            #pragma unroll
            for (int r = 0; r < 8; r++) {
                float4 xv = *(float4*)(&sT[(rbase + r) * 68 + k0]);
                acc[r] += xv.x * w0 + xv.y * w1 + xv.z * w2 + xv.w * w3;
            }
        }
        #pragma unroll
        for (int r = 0; r < 8; r++) {
            float t = acc[r];
            float sil = t / (1.f + __expf(-t));
            float v = sil * gw2v;
            #pragma unroll
            for (int o = 16; o > 0; o >>= 1) v += __shfl_xor_sync(0xffffffffu, v, o);
            int row = n0 + rbase + r;
            if (lane == 0 && row < n) gate[row] = v + gb2v;
        }
    }
}

// ---------------------------------------------------------------------------
// Per-graph softmax attention pool over fp16 features
// (batch sorted -> binary-search segment; no atomics)
// ---------------------------------------------------------------------------
__global__ void k_pool(const __half* __restrict__ X, const float* __restrict__ gate,
                       const int* __restrict__ batch, float* __restrict__ out, int n) {
    int g = blockIdx.x;
    int tid = threadIdx.x;  // 64 threads

    int lo = 0, hi = n;
    while (lo < hi) { int mid = (lo + hi) >> 1; if (batch[mid] < g) lo = mid + 1; else hi = mid; }
    int start = lo;
    lo = start; hi = n;
    while (lo < hi) { int mid = (lo + hi) >> 1; if (batch[mid] < g + 1) lo = mid + 1; else hi = mid; }
    int end = lo;

    if (start >= end) { out[(size_t)g * 64 + tid] = 0.f; return; }

    __shared__ float wred[2];
    __shared__ float sw[128];
    float m = -3.402823e38f;
    for (int i = start + tid; i < end; i += 64) m = fmaxf(m, gate[i]);
    #pragma unroll
    for (int o = 16; o > 0; o >>= 1) m = fmaxf(m, __shfl_xor_sync(0xffffffffu, m, o));
    if ((tid & 31) == 0) wred[tid >> 5] = m;
    __syncthreads();
    m = fmaxf(wred[0], wred[1]);
    __syncthreads();
    float s = 0.f;
    for (int i = start + tid; i < end; i += 64) s += __expf(gate[i] - m);
    #pragma unroll
    for (int o = 16; o > 0; o >>= 1) s += __shfl_xor_sync(0xffffffffu, s, o);
    if ((tid & 31) == 0) wred[tid >> 5] = s;
    __syncthreads();
    float inv = 1.f / (wred[0] + wred[1]);

    float acc = 0.f;
    for (int chunk = start; chunk < end; chunk += 128) {
        int cnt = min(128, end - chunk);
        __syncthreads();
        for (int i = tid; i < cnt; i += 64) sw[i] = __expf(gate[chunk + i] - m);
        __syncthreads();
        for (int k = 0; k < cnt; k++)
            acc += sw[k] * __half2float(X[(size_t)(chunk + k) * 64 + tid]);
    }
    out[(size_t)g * 64 + tid] = acc * inv;
}

// ---------------------------------------------------------------------------
extern "C" void kernel_launch(void* const* d_in, const int* in_sizes, int n_in,
                              void* d_out, int out_size) {
    const float* x   = (const float*)d_in[0];
    const int*   ei  = (const int*)d_in[1];
    const int*   bat = (const int*)d_in[2];
    const float* W1  = (const float*)d_in[3];
    const float* b1  = (const float*)d_in[4];
    const float* W2  = (const float*)d_in[5];
    const float* b2  = (const float*)d_in[6];
    const float* eps = (const float*)d_in[7];
    const float* lng = (const float*)d_in[8];
    const float* lnb = (const float*)d_in[9];
    const float* gw1 = (const float*)d_in[10];
    const float* gb1 = (const float*)d_in[11];
    const float* gw2 = (const float*)d_in[12];
    const float* gb2 = (const float*)d_in[13];
    float* out = (float*)d_out;

    int n = in_sizes[0] / DDIM;
    int e = in_sizes[1] / 2;
    int g = out_size / DDIM;
    const int* src = ei;
    const int* dst = ei + e;

    float *ggate;
    __half *ha, *hb;
    int *deg, *rsa, *pos, *csr;
    cudaGetSymbolAddress((void**)&ha, g_ha);
    cudaGetSymbolAddress((void**)&hb, g_hb);
    cudaGetSymbolAddress((void**)&ggate, g_gate);
    cudaGetSymbolAddress((void**)&deg, g_deg);
    cudaGetSymbolAddress((void**)&rsa, g_rs);
    cudaGetSymbolAddress((void**)&pos, g_pos);
    cudaGetSymbolAddress((void**)&csr, g_csr);

    int total4 = n * (DDIM / 4);
    k_pre<<<(total4 + 255) / 256, 256>>>(x, hb, deg, total4, n);
    k_hist<<<(e + 255) / 256, 256>>>(dst, deg, pos, e);
    k_alloc<<<(n + 255) / 256, 256>>>(deg, rsa, n);
    k_fill<<<(e + 255) / 256, 256>>>(src, dst, pos, rsa, csr, e);

    int nblk = (n + 63) / 64;
    k_mlp<<<nblk, 256>>>(hb, deg, rsa, csr, eps, 0,
                         W1, b1, W2, b2, lng, lnb,
                         gw1, gb1, gw2, gb2, ggate, 0, ha, n);
    k_mlp<<<nblk, 256>>>(ha, deg, rsa, csr, eps, 1,
                         W1 + 4096, b1 + 64, W2 + 4096, b2 + 64,
                         lng + 64, lnb + 64,
                         gw1, gb1, gw2, gb2, ggate, 0, hb, n);
    k_mlp<<<nblk, 256>>>(hb, deg, rsa, csr, eps, 2,
                         W1 + 8192, b1 + 128, W2 + 8192, b2 + 128,
                         lng + 128, lnb + 128,
                         gw1, gb1, gw2, gb2, ggate, 1, ha, n);

    k_pool<<<g, 64>>>(ha, ggate, bat, out, n);
}